// round 15
// baseline (speedup 1.0000x reference)
#include <cuda_runtime.h>
#include <cuda_bf16.h>
#include <cstdint>

// TrueHigherOrderAttention — degenerate-mask reduction.
// The reference mask forces j==i and k==i, so the (j,k) softmax is an exact
// one-hot at (i,i,i):   out = ((x @ Wv1^T) .* (x @ Wv2^T)) @ Wc^T
//
// R15 = R14 (16.9us: bf16 m16n8k16 3-term, ldmatrix, RS=36, double buffer,
// frag pipeline) at 16x16 tiles / 64 threads / 512 CTAs, launch_bounds(64,6):
// every CTA resident in one wave (~3.5 chains/SM) so each serial chunk-chain's
// exposed LDG/barrier latency is covered by 2-3 sibling chains. Parity-split
// accumulators dropped (proven neutral) to cut register pressure.

constexpr int T   = 256;
constexpr int C   = 512;
constexpr int KC  = 64;          // k floats per chunk
constexpr int NCH = 8;
constexpr int RS  = 36;          // row stride in words (32 hi-words + pad 4)
constexpr int TW  = 16 * RS;     // one tier (16 rows) = 576 words

__device__ float g_tmp[T * C];

__device__ __forceinline__ void mma16(float* d, const uint32_t* a, const uint32_t* b)
{
    asm("mma.sync.aligned.m16n8k16.row.col.f32.bf16.bf16.f32 "
        "{%0,%1,%2,%3}, {%4,%5,%6,%7}, {%8,%9}, {%0,%1,%2,%3};"
        : "+f"(d[0]), "+f"(d[1]), "+f"(d[2]), "+f"(d[3])
        : "r"(a[0]), "r"(a[1]), "r"(a[2]), "r"(a[3]),
          "r"(b[0]), "r"(b[1]));
}

__device__ __forceinline__ void ldsm4(uint32_t* r, uint32_t addr)
{
    asm volatile("ldmatrix.sync.aligned.m8n8.x4.shared.b16 {%0,%1,%2,%3}, [%4];"
                 : "=r"(r[0]), "=r"(r[1]), "=r"(r[2]), "=r"(r[3]) : "r"(addr));
}
__device__ __forceinline__ void ldsm2(uint32_t* r, uint32_t addr)
{
    asm volatile("ldmatrix.sync.aligned.m8n8.x2.shared.b16 {%0,%1}, [%2];"
                 : "=r"(r[0]), "=r"(r[1]) : "r"(addr));
}

// OUT = (X @ W1^T) [ .* (X @ W2^T) if DUAL ]  on a 16x16 tile, 2xBF16 3-term.
// X: [M x C] row-major; W: [C x C] row-major (output col n = row n of W).
// Tiers (words): A_hi 0, A_lo TW, B1_hi 2TW, B1_lo 3TW, B2_hi 4TW, B2_lo 5TW.
template <bool DUAL>
__global__ __launch_bounds__(64, 6)
void gemm_bf16_kernel(const float* __restrict__ X,
                      const float* __restrict__ W1,
                      const float* __restrict__ W2,
                      float* __restrict__ OUT)
{
    extern __shared__ uint32_t sm[];
    constexpr int BUFW = (DUAL ? 6 : 4) * TW;    // words per double-buffer half

    const int i0   = blockIdx.x * 16;
    const int n0   = blockIdx.y * 16;
    const int tid  = threadIdx.x;
    const int lane = tid & 31;
    const int wid  = tid >> 5;           // 0..1

    // ---- loader: lq = float4 within row (0..15), base row tid>>4 (0..3) ----
    const int lq = tid & 15;
    const int r4 = tid >> 4;

    float4 xr[4], w1r[4], w2r[4];
    auto gload = [&](int kb) {
#pragma unroll
        for (int it = 0; it < 4; it++) {
            const int row = r4 + 4 * it;
            xr [it] = *(const float4*)&X [(i0 + row) * C + kb + 4 * lq];
            w1r[it] = *(const float4*)&W1[(n0 + row) * C + kb + 4 * lq];
            if (DUAL)
                w2r[it] = *(const float4*)&W2[(n0 + row) * C + kb + 4 * lq];
        }
    };

    // split float4 -> bf16 hi pair-words + lo residual; STS.64 per tier.
    // 16 lanes share a row, words 2lq..2lq+1 -> conflict-free.
    auto stile = [&](uint32_t* tile, const float4& v, int row) {
        const __nv_bfloat162 h0 = __floats2bfloat162_rn(v.x, v.y);
        const __nv_bfloat162 h1 = __floats2bfloat162_rn(v.z, v.w);
        const float lx = v.x - __bfloat162float(h0.x);
        const float ly = v.y - __bfloat162float(h0.y);
        const float lz = v.z - __bfloat162float(h1.x);
        const float lw = v.w - __bfloat162float(h1.y);
        const __nv_bfloat162 l0 = __floats2bfloat162_rn(lx, ly);
        const __nv_bfloat162 l1 = __floats2bfloat162_rn(lz, lw);
        uint32_t* dst = tile + row * RS + 2 * lq;
        *(uint2*)dst        = make_uint2(*(const uint32_t*)&h0, *(const uint32_t*)&h1);
        *(uint2*)(dst + TW) = make_uint2(*(const uint32_t*)&l0, *(const uint32_t*)&l1);
    };

    auto split_sts = [&](uint32_t* buf) {
#pragma unroll
        for (int it = 0; it < 4; it++) {
            const int row = r4 + 4 * it;
            stile(buf,          xr [it], row);
            stile(buf + 2 * TW, w1r[it], row);
            if (DUAL) stile(buf + 4 * TW, w2r[it], row);
        }
    };

    // ---- compute mapping: 2 warps = 2(n); warp tile m16 x n8 x k16 ----
    const int N0 = wid * 8;
    const int aoff = (lane & 15) * RS + 4 * (lane >> 4);
    const int boff = (N0 + (lane & 7)) * RS + 4 * ((lane >> 3) & 1);

    const uint32_t smbase = (uint32_t)__cvta_generic_to_shared(sm);

    struct Frag {
        uint32_t Ah[4], Al[4], B1h[2], B1l[2], B2h[2], B2l[2];
    };
    Frag fr[2];

    auto ldfrag = [&](uint32_t bufb, int s, Frag& f) {
        const uint32_t so = 32 * s;   // 8 words per k16 step
        ldsm4(f.Ah, bufb + 4 * aoff + so);
        ldsm4(f.Al, bufb + 4 * (TW + aoff) + so);
        ldsm2(f.B1h, bufb + 4 * (2 * TW + boff) + so);
        ldsm2(f.B1l, bufb + 4 * (3 * TW + boff) + so);
        if (DUAL) {
            ldsm2(f.B2h, bufb + 4 * (4 * TW + boff) + so);
            ldsm2(f.B2l, bufb + 4 * (5 * TW + boff) + so);
        }
    };

    float p[3][4] = {}, q[3][4] = {};

    // ---- prologue: fill buffer 0 ----
    gload(0);
    split_sts(sm);
    __syncthreads();

    for (int ch = 0; ch < NCH; ch++) {
        const uint32_t bufb = smbase + (ch & 1) * (BUFW * 4);
        if (ch + 1 < NCH) gload((ch + 1) * KC);   // LDG early, long latency

        ldfrag(bufb, 0, fr[0]);
#pragma unroll
        for (int s = 0; s < 4; s++) {
            if (s < 3) ldfrag(bufb, s + 1, fr[(s + 1) & 1]);
            Frag& f = fr[s & 1];
            mma16(p[0], f.Ah, f.B1h);
            if (DUAL) mma16(q[0], f.Ah, f.B2h);
            mma16(p[1], f.Ah, f.B1l);
            if (DUAL) mma16(q[1], f.Ah, f.B2l);
            mma16(p[2], f.Al, f.B1h);
            if (DUAL) mma16(q[2], f.Al, f.B2h);
        }

        if (ch + 1 < NCH) {
            split_sts(sm + ((ch + 1) & 1) * BUFW);
            __syncthreads();
        }
    }

    // ---- epilogue: merge terms, (optional) product, store ----
    float P[4], Q[4];
#pragma unroll
    for (int i = 0; i < 4; i++) {
        P[i] = p[0][i] + p[1][i] + p[2][i];
        if (DUAL) Q[i] = q[0][i] + q[1][i] + q[2][i];
    }
    const int row = i0 + (lane >> 2);
    const int col = n0 + N0 + 2 * (lane & 3);
    float2 v0, v1;
    if (DUAL) {
        v0 = make_float2(P[0] * Q[0], P[1] * Q[1]);
        v1 = make_float2(P[2] * Q[2], P[3] * Q[3]);
    } else {
        v0 = make_float2(P[0], P[1]);
        v1 = make_float2(P[2], P[3]);
    }
    *(float2*)&OUT[ row      * C + col] = v0;
    *(float2*)&OUT[(row + 8) * C + col] = v1;
}

extern "C" void kernel_launch(void* const* d_in, const int* in_sizes, int n_in,
                              void* d_out, int out_size)
{
    // metadata order: x, Wq, Wk1, Wk2, Wv1, Wv2, Wc
    const float* x   = (const float*)d_in[0];
    const float* Wv1 = (const float*)d_in[4];
    const float* Wv2 = (const float*)d_in[5];
    const float* Wc  = (const float*)d_in[6];
    float* out = (float*)d_out;

    float* tmp = nullptr;
    cudaGetSymbolAddress((void**)&tmp, g_tmp);

    const int sm1 = 2 * 6 * TW * 4;   // 27648 B (double-buffered, 3 tiles)
    const int sm2 = 2 * 4 * TW * 4;   // 18432 B
    cudaFuncSetAttribute(gemm_bf16_kernel<true>,
                         cudaFuncAttributeMaxDynamicSharedMemorySize, sm1);
    cudaFuncSetAttribute(gemm_bf16_kernel<false>,
                         cudaFuncAttributeMaxDynamicSharedMemorySize, sm2);

    dim3 grid(T / 16, C / 16);   // 16 x 32 = 512 CTAs, all resident
    gemm_bf16_kernel<true ><<<grid, 64, sm1>>>(x,   Wv1, Wv2,     tmp);
    gemm_bf16_kernel<false><<<grid, 64, sm2>>>(tmp, Wc,  nullptr, out);
}

// round 16
// speedup vs baseline: 1.0052x; 1.0052x over previous
#include <cuda_runtime.h>
#include <cuda_bf16.h>
#include <cstdint>

// TrueHigherOrderAttention — degenerate-mask reduction.
// The reference mask forces j==i and k==i, so the (j,k) softmax is an exact
// one-hot at (i,i,i):   out = ((x @ Wv1^T) .* (x @ Wv2^T)) @ Wc^T
//
// R16: FUSED single-kernel version of R14 (16.9us best). Evidence from R4/R7:
// every kernel launch in this harness costs ~4-5us regardless of body, so the
// 2-launch pipeline carries ~8-10us of pure overhead. One kernel, 256 CTAs x
// 128 threads: each CTA runs its stage1 tile, signals a per-rowblock counter,
// spins until its rowblock's 16 producer tiles are done, then runs its stage2
// tile (fine-grained dependency -> stages pipeline across rowblocks).
// Deadlock-safe: launch_bounds(128,2) + 46KB smem guarantees occupancy 2/SM,
// so all 256 CTAs are resident in wave 1 (296 slots). Counters are reset by
// the last CTA each launch (graph-replay safe). GEMM internals = R14
// verbatim: bf16 m16n8k16 3-term decomposition, ldmatrix, RS=36, double
// buffer, fragment pipeline.

constexpr int T   = 256;
constexpr int C   = 512;
constexpr int KC  = 64;          // k floats per chunk
constexpr int NCH = 8;
constexpr int RS  = 36;          // row stride in 32-bit words (64 bf16 + pad)
constexpr int AW  = 16 * RS;     // A tier words (16 rows)
constexpr int BW  = 32 * RS;     // B tier words (32 rows)

__device__ float    g_tmp[T * C];
__device__ unsigned g_cnt[16];   // per-rowblock stage1 completion counters
__device__ unsigned g_done;      // end-of-launch reset coordinator

__device__ __forceinline__ void mma16(float* d, const uint32_t* a, const uint32_t* b)
{
    asm("mma.sync.aligned.m16n8k16.row.col.f32.bf16.bf16.f32 "
        "{%0,%1,%2,%3}, {%4,%5,%6,%7}, {%8,%9}, {%0,%1,%2,%3};"
        : "+f"(d[0]), "+f"(d[1]), "+f"(d[2]), "+f"(d[3])
        : "r"(a[0]), "r"(a[1]), "r"(a[2]), "r"(a[3]),
          "r"(b[0]), "r"(b[1]));
}

__device__ __forceinline__ void ldsm4(uint32_t* r, uint32_t addr)
{
    asm volatile("ldmatrix.sync.aligned.m8n8.x4.shared.b16 {%0,%1,%2,%3}, [%4];"
                 : "=r"(r[0]), "=r"(r[1]), "=r"(r[2]), "=r"(r[3]) : "r"(addr));
}
__device__ __forceinline__ void ldsm2(uint32_t* r, uint32_t addr)
{
    asm volatile("ldmatrix.sync.aligned.m8n8.x2.shared.b16 {%0,%1}, [%2];"
                 : "=r"(r[0]), "=r"(r[1]) : "r"(addr));
}

// OUT = (X @ W1^T) [ .* (X @ W2^T) if DUAL ]  on a 16x32 tile, 2xBF16 3-term.
// X: [M x C] row-major; W: [C x C] row-major (output col n = row n of W).
template <bool DUAL>
__device__ __forceinline__
void gemm_tile(const float* __restrict__ X,
               const float* __restrict__ W1,
               const float* __restrict__ W2,
               float* __restrict__ OUT,
               int i0, int n0, uint32_t* sm)
{
    // tier layout (words): A_hi 0, A_lo AW, B1_hi 2AW, B1_lo 2AW+BW,
    //                      B2_hi 2AW+2BW, B2_lo 2AW+3BW
    constexpr int B1OFF = 2 * AW;
    constexpr int B2OFF = 2 * AW + 2 * BW;
    constexpr int BUFW  = DUAL ? (2 * AW + 4 * BW) : (2 * AW + 2 * BW);

    const int tid  = threadIdx.x;
    const int lane = tid & 31;
    const int wid  = tid >> 5;           // 0..3

    // ---- loader: q = tid&15 (float4 within chunk row), base row tid>>4 ----
    const int lq = tid & 15;
    const int lr = tid >> 4;             // 0..7

    float4 xr[2], w1r[4], w2r[4];
    auto gload = [&](int kb) {
#pragma unroll
        for (int it = 0; it < 2; it++)
            xr[it] = *(const float4*)&X[(i0 + lr + 8 * it) * C + kb + 4 * lq];
#pragma unroll
        for (int it = 0; it < 4; it++) {
            w1r[it] = *(const float4*)&W1[(n0 + lr + 8 * it) * C + kb + 4 * lq];
            if (DUAL)
                w2r[it] = *(const float4*)&W2[(n0 + lr + 8 * it) * C + kb + 4 * lq];
        }
    };

    // split float4 -> bf16 hi pair-words + lo residual; STS.64 each tier.
    // Phase = 16 lanes sharing one row, words 2q..2q+1 -> conflict-free.
    auto stile = [&](uint32_t* tile, int tierw, const float4& v, int row) {
        const __nv_bfloat162 h0 = __floats2bfloat162_rn(v.x, v.y);
        const __nv_bfloat162 h1 = __floats2bfloat162_rn(v.z, v.w);
        const float lx = v.x - __bfloat162float(h0.x);
        const float ly = v.y - __bfloat162float(h0.y);
        const float lz = v.z - __bfloat162float(h1.x);
        const float lw = v.w - __bfloat162float(h1.y);
        const __nv_bfloat162 l0 = __floats2bfloat162_rn(lx, ly);
        const __nv_bfloat162 l1 = __floats2bfloat162_rn(lz, lw);
        uint32_t* dst = tile + row * RS + 2 * lq;
        *(uint2*)dst           = make_uint2(*(const uint32_t*)&h0, *(const uint32_t*)&h1);
        *(uint2*)(dst + tierw) = make_uint2(*(const uint32_t*)&l0, *(const uint32_t*)&l1);
    };

    auto split_sts = [&](uint32_t* buf) {
#pragma unroll
        for (int it = 0; it < 2; it++)
            stile(buf, AW, xr[it], lr + 8 * it);
#pragma unroll
        for (int it = 0; it < 4; it++) {
            stile(buf + B1OFF, BW, w1r[it], lr + 8 * it);
            if (DUAL) stile(buf + B2OFF, BW, w2r[it], lr + 8 * it);
        }
    };

    // ---- compute mapping: 4 warps = 4(n); warp tile m16 x n8 x k16 ----
    const int N0 = wid * 8;
    const int aoff = (lane & 15) * RS + 4 * (lane >> 4);
    const int boff = (N0 + (lane & 7)) * RS + 4 * ((lane >> 3) & 1);

    const uint32_t smbase = (uint32_t)__cvta_generic_to_shared(sm);

    struct Frag {
        uint32_t Ah[4], Al[4], B1h[2], B1l[2], B2h[2], B2l[2];
    };
    Frag fr[2];

    auto ldfrag = [&](uint32_t bufb, int s, Frag& f) {
        const uint32_t so = 32 * s;   // 8 words per k16 step
        ldsm4(f.Ah, bufb + 4 * aoff + so);
        ldsm4(f.Al, bufb + 4 * (AW + aoff) + so);
        ldsm2(f.B1h, bufb + 4 * (B1OFF + boff) + so);
        ldsm2(f.B1l, bufb + 4 * (B1OFF + BW + boff) + so);
        if (DUAL) {
            ldsm2(f.B2h, bufb + 4 * (B2OFF + boff) + so);
            ldsm2(f.B2l, bufb + 4 * (B2OFF + BW + boff) + so);
        }
    };

    float p[3][4] = {}, q[3][4] = {};

    // ---- prologue: fill buffer 0 ----
    gload(0);
    split_sts(sm);
    __syncthreads();

    for (int ch = 0; ch < NCH; ch++) {
        const uint32_t bufb = smbase + (ch & 1) * (BUFW * 4);
        if (ch + 1 < NCH) gload((ch + 1) * KC);   // LDG early, long latency

        ldfrag(bufb, 0, fr[0]);
#pragma unroll
        for (int s = 0; s < 4; s++) {
            if (s < 3) ldfrag(bufb, s + 1, fr[(s + 1) & 1]);
            Frag& f = fr[s & 1];
            mma16(p[0], f.Ah, f.B1h);
            if (DUAL) mma16(q[0], f.Ah, f.B2h);
            mma16(p[1], f.Ah, f.B1l);
            if (DUAL) mma16(q[1], f.Ah, f.B2l);
            mma16(p[2], f.Al, f.B1h);
            if (DUAL) mma16(q[2], f.Al, f.B2h);
        }

        if (ch + 1 < NCH) {
            split_sts(sm + ((ch + 1) & 1) * BUFW);
            __syncthreads();
        }
    }

    // ---- epilogue: merge terms, (optional) product, store ----
    float P[4], Q[4];
#pragma unroll
    for (int i = 0; i < 4; i++) {
        P[i] = p[0][i] + p[1][i] + p[2][i];
        if (DUAL) Q[i] = q[0][i] + q[1][i] + q[2][i];
    }
    const int row = i0 + (lane >> 2);
    const int col = n0 + N0 + 2 * (lane & 3);
    float2 v0, v1;
    if (DUAL) {
        v0 = make_float2(P[0] * Q[0], P[1] * Q[1]);
        v1 = make_float2(P[2] * Q[2], P[3] * Q[3]);
    } else {
        v0 = make_float2(P[0], P[1]);
        v1 = make_float2(P[2], P[3]);
    }
    *(float2*)&OUT[ row      * C + col] = v0;
    *(float2*)&OUT[(row + 8) * C + col] = v1;
}

__global__ __launch_bounds__(128, 2)
void fused_kernel(const float* __restrict__ x,
                  const float* __restrict__ Wv1,
                  const float* __restrict__ Wv2,
                  const float* __restrict__ Wc,
                  float* __restrict__ tmp,
                  float* __restrict__ out)
{
    extern __shared__ uint32_t sm[];
    const int b  = blockIdx.x;
    const int ib = b >> 4;               // rowblock 0..15
    const int i0 = ib * 16;
    const int n0 = (b & 15) * 32;

    // ---- stage 1: tmp tile = (x@Wv1^T) .* (x@Wv2^T) ----
    gemm_tile<true>(x, Wv1, Wv2, tmp, i0, n0, sm);

    // ---- per-rowblock dependency barrier ----
    __syncthreads();                      // all stage1 STGs issued
    if (threadIdx.x == 0) {
        __threadfence();                  // tmp visible before signal
        atomicAdd(&g_cnt[ib], 1u);
        while (*(volatile unsigned*)&g_cnt[ib] < 16u)
            __nanosleep(32);
        __threadfence();                  // order subsequent reads
    }
    __syncthreads();

    // ---- stage 2: out tile = tmp @ Wc^T ----
    gemm_tile<false>(tmp, Wc, nullptr, out, i0, n0, sm);

    // ---- reset counters for the next (graph-replayed) launch ----
    __syncthreads();
    if (threadIdx.x == 0) {
        const unsigned old = atomicAdd(&g_done, 1u);
        if (old == 255u) {                // last CTA through: everyone passed
#pragma unroll
            for (int i = 0; i < 16; i++) g_cnt[i] = 0u;
            g_done = 0u;
            __threadfence();
        }
    }
}

extern "C" void kernel_launch(void* const* d_in, const int* in_sizes, int n_in,
                              void* d_out, int out_size)
{
    // metadata order: x, Wq, Wk1, Wk2, Wv1, Wv2, Wc
    const float* x   = (const float*)d_in[0];
    const float* Wv1 = (const float*)d_in[4];
    const float* Wv2 = (const float*)d_in[5];
    const float* Wc  = (const float*)d_in[6];
    float* out = (float*)d_out;

    float* tmp = nullptr;
    cudaGetSymbolAddress((void**)&tmp, g_tmp);

    const int smb = 2 * (2 * AW + 4 * BW) * 4;   // 46080 B (stage1 layout, max)
    cudaFuncSetAttribute(fused_kernel,
                         cudaFuncAttributeMaxDynamicSharedMemorySize, smb);

    fused_kernel<<<256, 128, smb>>>(x, Wv1, Wv2, Wc, tmp, out);
}